// round 17
// baseline (speedup 1.0000x reference)
#include <cuda_runtime.h>
#include <cuda_bf16.h>

#define H      256
#define OUTN   200
#define DIN    20
#define TSTEPS 150

#define MSTR   264      // membrane row stride (floats), layers 1-4
#define M5STR  208      // layer-5 membrane stride

// dynamic smem byte offsets
#define SM_M1   0
#define SM_M2   33792
#define SM_M3   67584
#define SM_M4   101376
#define SM_M5   135168              // 32 x 208 x 4 = 26624
#define SM_SB0  161792              // spikes bf16 [32][256] = 16384
#define SM_SB1  178176
#define SM_X    194560              // x [32][20] f32 = 2560
#define SM_ACC  197120              // softmax acc [32][200] f32 = 25600
#define SM_BIAS 222720              // b1..b4 [4][256] f32 = 4096
#define SM_TOT  226816

// B-fragments: [layer(4)][kc(16)][term(3)][nt(32)][lane(32)][2] u32
// +16K u32 pad: distance-2 prefetch reads up to ~108K u32 past the last
// layer base (kc+2=17) — discarded values, must stay in-bounds.
__device__ __align__(16) unsigned g_Wf[393216 + 16384];
__device__ float g_W1t[DIN * H];    // W1 transposed fp32 for scalar layer 1

__device__ __forceinline__ unsigned smem_u32(const void* p) {
    unsigned a;
    asm("{ .reg .u64 t; cvta.to.shared.u64 t, %1; cvt.u32.u64 %0, t; }"
        : "=r"(a) : "l"(p));
    return a;
}
__device__ __forceinline__ void ldsm4(unsigned& a0, unsigned& a1,
                                      unsigned& a2, unsigned& a3, unsigned addr) {
    asm volatile("ldmatrix.sync.aligned.m8n8.x4.shared.b16 {%0,%1,%2,%3}, [%4];"
        : "=r"(a0), "=r"(a1), "=r"(a2), "=r"(a3) : "r"(addr));
}
__device__ __forceinline__ void mma_bf16(float* c, unsigned a0, unsigned a1,
                                         unsigned a2, unsigned a3,
                                         unsigned b0, unsigned b1) {
    asm volatile("mma.sync.aligned.m16n8k16.row.col.f32.bf16.bf16.f32 "
        "{%0,%1,%2,%3}, {%4,%5,%6,%7}, {%8,%9}, {%0,%1,%2,%3};"
        : "+f"(c[0]), "+f"(c[1]), "+f"(c[2]), "+f"(c[3])
        : "r"(a0), "r"(a1), "r"(a2), "r"(a3), "r"(b0), "r"(b1));
}

// exact 3-term bf16 decomposition (w = t0+t1+t2 + eps, |eps| ~ 2^-25|w|)
__device__ __forceinline__ unsigned short bterm(float w, int term) {
    __nv_bfloat16 h0 = __float2bfloat16(w);
    if (term == 0) return *(unsigned short*)&h0;
    float r1 = w - __bfloat162float(h0);
    __nv_bfloat16 h1 = __float2bfloat16(r1);
    if (term == 1) return *(unsigned short*)&h1;
    float r2 = r1 - __bfloat162float(h1);
    __nv_bfloat16 h2 = __float2bfloat16(r2);
    return *(unsigned short*)&h2;
}

__global__ void prep(const float* __restrict__ W1, const float* __restrict__ W2,
                     const float* __restrict__ W3, const float* __restrict__ W4,
                     const float* __restrict__ WO) {
    int idx = blockIdx.x * blockDim.x + threadIdx.x;
    if (idx < 393216) {
        int layer = idx / 98304; int r = idx % 98304;
        int kc = r / 6144;  r %= 6144;
        int term = r / 2048; r %= 2048;
        int nt = r >> 6;    r &= 63;
        int lane = r >> 1,  hb = r & 1;
        int n = nt * 8 + (lane >> 2);
        int k = kc * 16 + ((lane & 3) << 1) + hb * 8;
        const float* src = (layer == 0) ? W2 : (layer == 1) ? W3 : (layer == 2) ? W4 : WO;
        int nlim = (layer == 3) ? OUTN : H;
        float w0 = (n < nlim) ? src[n * H + k]     : 0.f;
        float w1 = (n < nlim) ? src[n * H + k + 1] : 0.f;
        g_Wf[idx] = (unsigned)bterm(w0, term) | ((unsigned)bterm(w1, term) << 16);
    } else if (idx < 393216 + DIN * H) {
        int r = idx - 393216; int i = r >> 8, j = r & 255;
        g_W1t[i * H + j] = W1[j * DIN + i];
    }
}

// One MMA layer, 16-warp split: warp w owns 2 n8-tiles (cols w*16..w*16+15),
// acc[mt][q][4]. Distance-2 double-buffered prefetch for A (ldsm) and B (L2),
// period-2 slots under unroll 2 (rotation renames away).
__device__ __forceinline__ void mma_layer(float acc[2][2][4],
        const unsigned* __restrict__ Wf, unsigned sbu, int w, int lane) {
#pragma unroll
    for (int mt = 0; mt < 2; mt++)
#pragma unroll
        for (int q = 0; q < 2; q++)
#pragma unroll
            for (int c = 0; c < 4; c++) acc[mt][q][c] = 0.f;

    const unsigned* bp = Wf + (w * 2) * 64 + lane * 2;
    unsigned arow = lane & 15;
    unsigned sw   = (arow & 7) << 4;
    unsigned koff = (lane >> 4) * 16;
    unsigned a0addr = sbu + arow * 512;
    unsigned a1addr = sbu + (16 + arow) * 512;

    unsigned A[2][2][4];    // [slot][mt][frag]
    uint2    B[2][6];       // [slot][term*2+q]
#pragma unroll
    for (int s = 0; s < 2; s++) {
        unsigned kb = (unsigned)(s * 32) + koff;
        ldsm4(A[s][0][0], A[s][0][1], A[s][0][2], A[s][0][3], a0addr + (kb ^ sw));
        ldsm4(A[s][1][0], A[s][1][1], A[s][1][2], A[s][1][3], a1addr + (kb ^ sw));
#pragma unroll
        for (int t = 0; t < 3; t++)
#pragma unroll
            for (int q = 0; q < 2; q++)
                B[s][t * 2 + q] = *(const uint2*)(bp + (s * 3 + t) * 2048 + q * 64);
    }

#pragma unroll 2
    for (int kc = 0; kc < 16; kc++) {
        int sl = kc & 1;
#pragma unroll
        for (int t = 0; t < 3; t++)
#pragma unroll
            for (int q = 0; q < 2; q++) {
                uint2 b = B[sl][t * 2 + q];
                mma_bf16(acc[0][q], A[sl][0][0], A[sl][0][1], A[sl][0][2], A[sl][0][3], b.x, b.y);
                mma_bf16(acc[1][q], A[sl][1][0], A[sl][1][1], A[sl][1][2], A[sl][1][3], b.x, b.y);
            }
        // prefetch kc+2 into the slot just consumed (overruns -> pad/smem, discarded)
        unsigned kb = (unsigned)((kc + 2) * 32) + koff;
        ldsm4(A[sl][0][0], A[sl][0][1], A[sl][0][2], A[sl][0][3], a0addr + (kb ^ sw));
        ldsm4(A[sl][1][0], A[sl][1][1], A[sl][1][2], A[sl][1][3], a1addr + (kb ^ sw));
#pragma unroll
        for (int t = 0; t < 3; t++)
#pragma unroll
            for (int q = 0; q < 2; q++)
                B[sl][t * 2 + q] = *(const uint2*)(bp + (unsigned)(((kc + 2) * 3 + t) * 2048 + q * 64));
    }
}

// hidden-layer epilogue: bias add, leaky (reset from PREVIOUS membrane), spike -> swizzled Sb
__device__ __forceinline__ void epi_hidden(float acc[2][2][4], float* __restrict__ mb,
        const float* __restrict__ bsh, unsigned sbo, int w, int lane) {
    int r0 = lane >> 2, cp = (lane & 3) * 2, nb = w * 16;
#pragma unroll
    for (int mt = 0; mt < 2; mt++)
#pragma unroll
        for (int q = 0; q < 2; q++) {
            int col = nb + q * 8 + cp;
            float b0 = bsh[col], b1 = bsh[col + 1];
#pragma unroll
            for (int h = 0; h < 2; h++) {
                int row = mt * 16 + r0 + h * 8;
                float i0 = acc[mt][q][h * 2 + 0] + b0;
                float i1 = acc[mt][q][h * 2 + 1] + b1;
                float* mp = mb + row * MSTR + col;
                float m0 = mp[0], m1 = mp[1];
                float n0 = 0.9f * m0 + i0 - (m0 > 1.f ? 1.f : 0.f);
                float n1 = 0.9f * m1 + i1 - (m1 > 1.f ? 1.f : 0.f);
                mp[0] = n0; mp[1] = n1;
                unsigned sp = (n0 > 1.f ? 0x3F80u : 0u) | (n1 > 1.f ? 0x3F800000u : 0u);
                unsigned ad = sbo + row * 512 + (((unsigned)(col * 2)) ^ ((row & 7) << 4));
                asm volatile("st.shared.b32 [%0], %1;" :: "r"(ad), "r"(sp));
            }
        }
}

// output-layer epilogue: no bias, no spike; cols >= 200 skipped
__device__ __forceinline__ void epi_out(float acc[2][2][4], float* __restrict__ mb,
                                        int w, int lane) {
    int r0 = lane >> 2, cp = (lane & 3) * 2, nb = w * 16;
#pragma unroll
    for (int mt = 0; mt < 2; mt++)
#pragma unroll
        for (int q = 0; q < 2; q++) {
            int col = nb + q * 8 + cp;
            if (col < OUTN) {
#pragma unroll
                for (int h = 0; h < 2; h++) {
                    int row = mt * 16 + r0 + h * 8;
                    float i0 = acc[mt][q][h * 2 + 0];
                    float i1 = acc[mt][q][h * 2 + 1];
                    float* mp = mb + row * M5STR + col;
                    float m0 = mp[0], m1 = mp[1];
                    mp[0] = 0.9f * m0 + i0 - (m0 > 1.f ? 1.f : 0.f);
                    mp[1] = 0.9f * m1 + i1 - (m1 > 1.f ? 1.f : 0.f);
                }
            }
        }
}

__global__ void __launch_bounds__(512, 1)
snn_main(const float* __restrict__ x,
         const float* __restrict__ b1, const float* __restrict__ b2,
         const float* __restrict__ b3, const float* __restrict__ b4,
         float* __restrict__ out) {
    extern __shared__ char sm[];
    float* M1f  = (float*)(sm + SM_M1);
    float* M2f  = (float*)(sm + SM_M2);
    float* M3f  = (float*)(sm + SM_M3);
    float* M4f  = (float*)(sm + SM_M4);
    float* M5f  = (float*)(sm + SM_M5);
    float* xsh  = (float*)(sm + SM_X);
    float* accs = (float*)(sm + SM_ACC);
    float* bsh  = (float*)(sm + SM_BIAS);

    const int tid  = threadIdx.x;
    const int w    = tid >> 5, lane = tid & 31;
    const int start = blockIdx.x * 32;
    const unsigned smb = smem_u32(sm);
    const unsigned SB0 = smb + SM_SB0, SB1 = smb + SM_SB1;

    // stage biases; zero membranes + softmax acc
    if (tid < 256) { bsh[tid] = b1[tid]; bsh[256 + tid] = b2[tid]; }
    else           { int j = tid - 256; bsh[512 + j] = b3[j]; bsh[768 + j] = b4[j]; }
    for (int i = tid; i < (SM_SB0 / 4); i += 512) ((float*)sm)[i] = 0.f;
    for (int i = tid; i < 32 * OUTN; i += 512) accs[i] = 0.f;

    // x staging: 640 elems, 2 slots/thread, pointer affine in t
    const float* xp[2]; int soff[2]; bool hs[2]; float xr[2];
#pragma unroll
    for (int s = 0; s < 2; s++) {
        int idx = tid + 512 * s;
        hs[s] = (idx < 32 * DIN);
        int row = idx / DIN, ii = idx - row * DIN;
        xp[s] = hs[s] ? (x + (size_t)(start + row) * (TSTEPS * DIN) + ii) : x;
        soff[s] = row * DIN + ii;
        xr[s] = xp[s][0];
    }

    // layer-1 scalar weights (K=20): thread = (neuron tid&255, row-half tid>>8)
    const int j1n = tid & 255;
    const int rh  = (tid >> 8) * 16;
    float wv[DIN];
#pragma unroll
    for (int i = 0; i < DIN; i++) wv[i] = g_W1t[i * H + j1n];
    const float bj1 = b1[j1n];

    float acc[2][2][4];
    __syncthreads();

    for (int t = 0; t < TSTEPS; t++) {
        // commit x_t, then prefetch x_{t+1}
#pragma unroll
        for (int s = 0; s < 2; s++) if (hs[s]) xsh[soff[s]] = xr[s];
        __syncthreads();
        if (t + 1 < TSTEPS) {
#pragma unroll
            for (int s = 0; s < 2; s++) xr[s] = xp[s][(t + 1) * DIN];
        }

        // ---- layer 1, scalar fp32 (exact): 16 rows per thread ----
        {
#pragma unroll 4
            for (int r = rh; r < rh + 16; r++) {
                const float* xrow = xsh + r * DIN;
                float s = 0.f;
#pragma unroll
                for (int i = 0; i < DIN; i++) s += wv[i] * xrow[i];
                float* mp = M1f + r * MSTR + j1n;
                float m = mp[0];
                float n = 0.9f * m + (s + bj1) - (m > 1.f ? 1.f : 0.f);
                mp[0] = n;
                unsigned short sv = (n > 1.f) ? (unsigned short)0x3F80 : (unsigned short)0;
                unsigned ad = SB0 + r * 512 + (((unsigned)(j1n * 2)) ^ ((r & 7) << 4));
                asm volatile("st.shared.b16 [%0], %1;" :: "r"(ad), "h"(sv));
            }
        }
        __syncthreads();

        mma_layer(acc, g_Wf,          SB0, w, lane);
        epi_hidden(acc, M2f, bsh + 256, SB1, w, lane);
        __syncthreads();
        mma_layer(acc, g_Wf +  98304, SB1, w, lane);
        epi_hidden(acc, M3f, bsh + 512, SB0, w, lane);
        __syncthreads();
        mma_layer(acc, g_Wf + 196608, SB0, w, lane);
        epi_hidden(acc, M4f, bsh + 768, SB1, w, lane);
        __syncthreads();
        mma_layer(acc, g_Wf + 294912, SB1, w, lane);
        epi_out(acc, M5f, w, lane);
        __syncthreads();

        if (t > 50) {
            // warp handles rows w*2, w*2+1
#pragma unroll
            for (int q = 0; q < 2; q++) {
                const float* row = M5f + (w * 2 + q) * M5STR;
                float* arow = accs + (w * 2 + q) * OUTN;
                float v[7]; float vmax = -3.0e38f;
#pragma unroll
                for (int k = 0; k < 7; k++) {
                    int jj = lane + 32 * k;
                    v[k] = (jj < OUTN) ? row[jj] : -3.0e38f;
                    vmax = fmaxf(vmax, v[k]);
                }
#pragma unroll
                for (int o = 16; o; o >>= 1) vmax = fmaxf(vmax, __shfl_xor_sync(0xffffffffu, vmax, o));
                float e[7]; float ssum = 0.f;
#pragma unroll
                for (int k = 0; k < 7; k++) {
                    int jj = lane + 32 * k;
                    e[k] = (jj < OUTN) ? __expf(v[k] - vmax) : 0.f;
                    ssum += e[k];
                }
#pragma unroll
                for (int o = 16; o; o >>= 1) ssum += __shfl_xor_sync(0xffffffffu, ssum, o);
                float inv = 1.0f / ssum;
#pragma unroll
                for (int k = 0; k < 7; k++) {
                    int jj = lane + 32 * k;
                    if (jj < OUTN) arow[jj] += e[k] * inv;
                }
            }
        }
        // no extra barrier: next writes to xsh/M5/accs are ordered by the syncs above
    }

    __syncthreads();
    for (int idx = tid; idx < 32 * OUTN; idx += 512) {
        int r = idx / OUTN, c = idx - r * OUTN;
        out[(size_t)(start + r) * OUTN + c] = accs[idx];
    }
}

extern "C" void kernel_launch(void* const* d_in, const int* in_sizes, int n_in,
                              void* d_out, int out_size) {
    const float* x  = (const float*)d_in[0];
    const float* W1 = (const float*)d_in[1];
    const float* b1 = (const float*)d_in[2];
    const float* W2 = (const float*)d_in[3];
    const float* b2 = (const float*)d_in[4];
    const float* W3 = (const float*)d_in[5];
    const float* b3 = (const float*)d_in[6];
    const float* W4 = (const float*)d_in[7];
    const float* b4 = (const float*)d_in[8];
    const float* WO = (const float*)d_in[9];
    float* out = (float*)d_out;

    prep<<<(393216 + DIN * H + 255) / 256, 256>>>(W1, W2, W3, W4, WO);
    cudaFuncSetAttribute(snn_main, cudaFuncAttributeMaxDynamicSharedMemorySize, SM_TOT);
    snn_main<<<64, 512, SM_TOT>>>(x, b1, b2, b3, b4, out);
}